// round 10
// baseline (speedup 1.0000x reference)
#include <cuda_runtime.h>
#include <cuda_bf16.h>
#include <cuda_fp16.h>
#include <math.h>
#include <stdint.h>

// Problem constants
#define B_  2
#define S_  4096
#define D_  2048
#define H_  16
#define HD_ 128
#define MROWS (B_ * S_)   // 8192

// Scratch in __device__ globals (allocation-guard-safe)
__device__ float g_q [(size_t)MROWS * D_];
__device__ float g_k [(size_t)MROWS * D_];
__device__ float g_v [(size_t)MROWS * D_];
__device__ float g_ao[(size_t)MROWS * D_];

// ---------------------------------------------------------------------------
// helpers
// ---------------------------------------------------------------------------
__device__ __forceinline__ void mma_bf16(float* c, const uint32_t* a, const uint32_t* b) {
    asm volatile(
        "mma.sync.aligned.m16n8k16.row.col.f32.bf16.bf16.f32 "
        "{%0,%1,%2,%3}, {%4,%5,%6,%7}, {%8,%9}, {%0,%1,%2,%3};\n"
        : "+f"(c[0]), "+f"(c[1]), "+f"(c[2]), "+f"(c[3])
        : "r"(a[0]), "r"(a[1]), "r"(a[2]), "r"(a[3]), "r"(b[0]), "r"(b[1]));
}

__device__ __forceinline__ void mma_fp16(float* c, const uint32_t* a, const uint32_t* b) {
    asm volatile(
        "mma.sync.aligned.m16n8k16.row.col.f32.f16.f16.f32 "
        "{%0,%1,%2,%3}, {%4,%5,%6,%7}, {%8,%9}, {%0,%1,%2,%3};\n"
        : "+f"(c[0]), "+f"(c[1]), "+f"(c[2]), "+f"(c[3])
        : "r"(a[0]), "r"(a[1]), "r"(a[2]), "r"(a[3]), "r"(b[0]), "r"(b[1]));
}

__device__ __forceinline__ uint32_t packbf(float a, float b) {
    __nv_bfloat162 t = __floats2bfloat162_rn(a, b);
    return *(uint32_t*)&t;
}

__device__ __forceinline__ uint32_t packhf(float a, float b) {
    __half2 t = __floats2half2_rn(a, b);
    return *(uint32_t*)&t;
}

// ---------------------------------------------------------------------------
// 3-pass split-bf16 GEMM (error ~2^-16):  C[m][n] = sum_k A[m][k] * Bw[n][k]
// 128x128 tile, BK=32, 256 threads = 8 warps (2m x 4n), warp tile 64x32.
// mma.sync m16n8k16 bf16, double-buffered smem (words [128][LDTW], LDTW=20).
// ---------------------------------------------------------------------------
#define LDTW 20
#define GSTAGE (128 * LDTW)            // words per (array, stage)
#define GEMM_SMEM_WORDS (8 * GSTAGE)   // Ah,Al,Bh,Bl x 2 stages (81920 B)

__global__ void __launch_bounds__(256, 1) tbgemm3_nt(const float* __restrict__ A,
                                                     const float* __restrict__ Bw,
                                                     float* __restrict__ C,
                                                     int M, int N, int K)
{
    extern __shared__ uint32_t sg[];
    uint32_t* Ah = sg;                  // [2][128][LDTW]
    uint32_t* Al = Ah + 2 * GSTAGE;
    uint32_t* Bh = Al + 2 * GSTAGE;
    uint32_t* Bl = Bh + 2 * GSTAGE;

    const int tid    = threadIdx.x;
    const int warp   = tid >> 5;
    const int lane   = tid & 31;
    const int warp_m = warp >> 2;      // 0..1 -> m offset *64
    const int warp_n = warp & 3;       // 0..3 -> n offset *32
    const int g      = lane >> 2;      // group 0..7
    const int tig    = lane & 3;       // thread-in-group 0..3

    const int bm = blockIdx.y * 128;
    const int bn = blockIdx.x * 128;

    const int lrow = tid >> 3;         // 0..31
    const int lk   = (tid & 7) * 4;    // float element 0,4,...,28
    const int lkw  = (tid & 7) * 2;    // word index 0,2,...,14

    float c[4][4][4];
#pragma unroll
    for (int mi = 0; mi < 4; mi++)
#pragma unroll
        for (int ni = 0; ni < 4; ni++)
#pragma unroll
            for (int j = 0; j < 4; j++) c[mi][ni][j] = 0.0f;

    float4 av[4], bv[4];
#pragma unroll
    for (int r = 0; r < 4; r++) {
        av[r] = *(const float4*)(A  + (size_t)(bm + lrow + 32 * r) * K + lk);
        bv[r] = *(const float4*)(Bw + (size_t)(bn + lrow + 32 * r) * K + lk);
    }

    const int iters = K / 32;
    for (int it = 0; it < iters; it++) {
        const int st = (it & 1) * GSTAGE;

#pragma unroll
        for (int r = 0; r < 4; r++) {
            int base = st + (lrow + 32 * r) * LDTW + lkw;
            {
                float hx = __bfloat162float(__float2bfloat16(av[r].x));
                float hy = __bfloat162float(__float2bfloat16(av[r].y));
                float hz = __bfloat162float(__float2bfloat16(av[r].z));
                float hw = __bfloat162float(__float2bfloat16(av[r].w));
                Ah[base]     = packbf(hx, hy);
                Ah[base + 1] = packbf(hz, hw);
                Al[base]     = packbf(av[r].x - hx, av[r].y - hy);
                Al[base + 1] = packbf(av[r].z - hz, av[r].w - hw);
            }
            {
                float hx = __bfloat162float(__float2bfloat16(bv[r].x));
                float hy = __bfloat162float(__float2bfloat16(bv[r].y));
                float hz = __bfloat162float(__float2bfloat16(bv[r].z));
                float hw = __bfloat162float(__float2bfloat16(bv[r].w));
                Bh[base]     = packbf(hx, hy);
                Bh[base + 1] = packbf(hz, hw);
                Bl[base]     = packbf(bv[r].x - hx, bv[r].y - hy);
                Bl[base + 1] = packbf(bv[r].z - hz, bv[r].w - hw);
            }
        }
        __syncthreads();

        if (it + 1 < iters) {
            const int k0 = (it + 1) * 32;
#pragma unroll
            for (int r = 0; r < 4; r++) {
                av[r] = *(const float4*)(A  + (size_t)(bm + lrow + 32 * r) * K + k0 + lk);
                bv[r] = *(const float4*)(Bw + (size_t)(bn + lrow + 32 * r) * K + k0 + lk);
            }
        }

#pragma unroll
        for (int kk = 0; kk < 2; kk++) {
            uint32_t ahi[4][4], alo[4][4], bhi[4][2], blo[4][2];
#pragma unroll
            for (int mi = 0; mi < 4; mi++) {
                int row = warp_m * 64 + mi * 16;
                int base0 = st + (row + g)     * LDTW + kk * 8 + tig;
                int base1 = st + (row + 8 + g) * LDTW + kk * 8 + tig;
                ahi[mi][0] = Ah[base0];
                ahi[mi][1] = Ah[base1];
                ahi[mi][2] = Ah[base0 + 4];
                ahi[mi][3] = Ah[base1 + 4];
                alo[mi][0] = Al[base0];
                alo[mi][1] = Al[base1];
                alo[mi][2] = Al[base0 + 4];
                alo[mi][3] = Al[base1 + 4];
            }
#pragma unroll
            for (int ni = 0; ni < 4; ni++) {
                int col = warp_n * 32 + ni * 8;
                int base = st + (col + g) * LDTW + kk * 8 + tig;
                bhi[ni][0] = Bh[base];
                bhi[ni][1] = Bh[base + 4];
                blo[ni][0] = Bl[base];
                blo[ni][1] = Bl[base + 4];
            }
#pragma unroll
            for (int mi = 0; mi < 4; mi++)
#pragma unroll
                for (int ni = 0; ni < 4; ni++) {
                    mma_bf16(c[mi][ni], ahi[mi], bhi[ni]);
                    mma_bf16(c[mi][ni], ahi[mi], blo[ni]);
                    mma_bf16(c[mi][ni], alo[mi], bhi[ni]);
                }
        }
        __syncthreads();
    }

#pragma unroll
    for (int mi = 0; mi < 4; mi++) {
#pragma unroll
        for (int ni = 0; ni < 4; ni++) {
            int row0 = bm + warp_m * 64 + mi * 16 + g;
            int col  = bn + warp_n * 32 + ni * 8 + 2 * tig;
            *(float2*)&C[(size_t)row0 * N + col] =
                make_float2(c[mi][ni][0], c[mi][ni][1]);
            *(float2*)&C[(size_t)(row0 + 8) * N + col] =
                make_float2(c[mi][ni][2], c[mi][ni][3]);
        }
    }
}

// ---------------------------------------------------------------------------
// Per-head RMSNorm + RoPE, in place on q and k.
// ---------------------------------------------------------------------------
__global__ void __launch_bounds__(256) rmsnorm_rope(float* __restrict__ qp,
                                                    float* __restrict__ kp,
                                                    const float* __restrict__ freqs,
                                                    const float* __restrict__ wq,
                                                    const float* __restrict__ wk)
{
    float* ptr      = blockIdx.y ? kp : qp;
    const float* w  = blockIdx.y ? wk : wq;

    const int warp = threadIdx.x >> 5;
    const int lane = threadIdx.x & 31;
    const size_t row = (size_t)blockIdx.x * 8 + warp;   // 0 .. B*S*H-1
    const size_t bs  = row >> 4;                        // (b*S + s)

    float4 xv = *(float4*)&ptr[row * HD_ + lane * 4];
    float ss = xv.x * xv.x + xv.y * xv.y + xv.z * xv.z + xv.w * xv.w;
#pragma unroll
    for (int off = 16; off; off >>= 1) ss += __shfl_xor_sync(0xffffffffu, ss, off);
    float r = rsqrtf(ss * (1.0f / 128.0f) + 1e-5f);

    float4 wv = *(const float4*)&w[lane * 4];
    float nr0 = xv.x * r * wv.x;
    float ni0 = xv.y * r * wv.y;
    float nr1 = xv.z * r * wv.z;
    float ni1 = xv.w * r * wv.w;

    const float* f = freqs + bs * HD_;
    float c0 = f[2 * lane],     c1 = f[2 * lane + 1];
    float s0 = f[64 + 2 * lane], s1 = f[64 + 2 * lane + 1];

    float4 o;
    o.x = nr0 * c0 - ni0 * s0;
    o.y = nr0 * s0 + ni0 * c0;
    o.z = nr1 * c1 - ni1 * s1;
    o.w = nr1 * s1 + ni1 * c1;
    *(float4*)&ptr[row * HD_ + lane * 4] = o;
}

// ---------------------------------------------------------------------------
// fp16 tensor-core flash attention (m16n8k16, fp32 softmax/accum).
// Br=128 q rows per CTA, Bc=64 kv per tile, 8 warps x 16 rows.
// Fragment-major fp16x2-word smem layouts, conflict-free wide LDS:
//   Qf[w8][kk8][lane32][4 words]   (pre-scaled by 1/sqrt(hd))
//   Kf[kk8][nt8][lane32][2 words]
//   Vf[kk4][nt16][lane32][2 words]
// P fragments built directly from softmax registers (no smem roundtrip).
// ---------------------------------------------------------------------------
#define FQW (8 * 8 * 32 * 4)    // 8192 words
#define FKW (8 * 8 * 32 * 2)    // 4096 words
#define FVW (4 * 16 * 32 * 2)   // 4096 words
#define FA_SMEM_BYTES ((FQW + FKW + FVW) * 4)   // 65536 B

__global__ void __launch_bounds__(256, 1) flash_attn_fp16(const float* __restrict__ q,
                                                          const float* __restrict__ k,
                                                          const float* __restrict__ v,
                                                          float* __restrict__ out)
{
    extern __shared__ uint32_t smw[];
    uint32_t* Qf = smw;
    uint32_t* Kf = Qf + FQW;
    uint32_t* Vf = Kf + FKW;
    __half* Vh = (__half*)Vf;

    const int b   = blockIdx.z;
    const int h   = blockIdx.y;
    const int q0  = blockIdx.x * 128;
    const int tid = threadIdx.x;
    const int w   = tid >> 5;
    const int lane = tid & 31;
    const int g   = lane >> 2;
    const int tig = lane & 3;

    const float scale = 0.08838834764831845f;  // 1/sqrt(128)

    // ---- Load Q tile -> fragment-major fp16 words, pre-scaled ----
    for (int i = tid; i < 128 * 32; i += 256) {
        int r  = i >> 5;
        int c0 = (i & 31) * 4;
        float4 val = *(const float4*)&q[(size_t)(b * S_ + q0 + r) * D_ + h * HD_ + c0];
        int wd = r >> 4, gg = r & 15;
        int rowhi = gg >> 3, gd = gg & 7;
        int kk = c0 >> 4;
        int p0 = (c0 & 15) >> 1;            // 0,2,4,6
        uint32_t w0 = packhf(val.x * scale, val.y * scale);  // pair p0
        uint32_t w1 = packhf(val.z * scale, val.w * scale);  // pair p0+1
        int hi0 = p0 >> 2;                   // both pairs share hi
        int jb = hi0 * 2 + rowhi;
        int base = ((wd * 8 + kk) * 32) * 4 + jb;
        Qf[base + (4 * gd + (p0 & 3)) * 4]       = w0;
        Qf[base + (4 * gd + ((p0 + 1) & 3)) * 4] = w1;
    }

    float m[2], l[2], o[16][4];
    m[0] = m[1] = -INFINITY;
    l[0] = l[1] = 0.0f;
#pragma unroll
    for (int nt = 0; nt < 16; nt++)
#pragma unroll
        for (int j = 0; j < 4; j++) o[nt][j] = 0.0f;

    for (int kv0 = 0; kv0 < S_; kv0 += 64) {
        __syncthreads();   // Kf/Vf free (prev tile done); covers Qf on iter 0

        // ---- Load K,V tiles -> fragment-major fp16 words ----
        for (int i = tid; i < 64 * 32; i += 256) {
            int r  = i >> 5;
            int c0 = (i & 31) * 4;
            size_t gbase = (size_t)(b * S_ + kv0 + r) * D_ + h * HD_ + c0;
            // K: n = kv row (r), k = dim (c)
            {
                float4 val = *(const float4*)&k[gbase];
                int nt = r >> 3, gd = r & 7;
                int kk = c0 >> 4;
                int p0 = (c0 & 15) >> 1;
                int slot = p0 >> 2;
                uint32_t w0 = packhf(val.x, val.y);
                uint32_t w1 = packhf(val.z, val.w);
                int base = ((kk * 8 + nt) * 32) * 2 + slot;
                Kf[base + (4 * gd + (p0 & 3)) * 2]       = w0;
                Kf[base + (4 * gd + ((p0 + 1) & 3)) * 2] = w1;
            }
            // V: k = kv row (r), n = dim (c) -- half-word scatter
            {
                float4 val = *(const float4*)&v[gbase];
                int kk = r >> 4, kin = r & 15;
                int t = kin >> 1, halfw = kin & 1;
                int slot = t >> 2, tigp = t & 3;
                int nt = c0 >> 3;
                int g0 = c0 & 7;
                float vals[4] = {val.x, val.y, val.z, val.w};
#pragma unroll
                for (int j4 = 0; j4 < 4; j4++) {
                    int lanep = 4 * (g0 + j4) + tigp;
                    Vh[(((kk * 16 + nt) * 32 + lanep) * 2 + slot) * 2 + halfw] =
                        __float2half(vals[j4]);
                }
            }
        }
        __syncthreads();

        // ---- S = Q K^T (pre-scaled) ----
        float sc[8][4];
#pragma unroll
        for (int nt = 0; nt < 8; nt++)
#pragma unroll
            for (int j = 0; j < 4; j++) sc[nt][j] = 0.0f;

#pragma unroll
        for (int kk = 0; kk < 8; kk++) {
            uint4 a4 = *(const uint4*)&Qf[((w * 8 + kk) * 32 + lane) * 4];
            uint32_t a[4] = {a4.x, a4.y, a4.z, a4.w};
#pragma unroll
            for (int nt = 0; nt < 8; nt++) {
                uint2 b2 = *(const uint2*)&Kf[((kk * 8 + nt) * 32 + lane) * 2];
                uint32_t bb[2] = {b2.x, b2.y};
                mma_fp16(sc[nt], a, bb);
            }
        }

        // ---- online softmax (rows g and g+8 of this warp's 16-row block) ----
#pragma unroll
        for (int rh = 0; rh < 2; rh++) {
            int i0 = rh * 2;
            float rm = -INFINITY;
#pragma unroll
            for (int nt = 0; nt < 8; nt++)
                rm = fmaxf(rm, fmaxf(sc[nt][i0], sc[nt][i0 + 1]));
            rm = fmaxf(rm, __shfl_xor_sync(0xffffffffu, rm, 1));
            rm = fmaxf(rm, __shfl_xor_sync(0xffffffffu, rm, 2));
            float mnew = fmaxf(m[rh], rm);
            float alpha = __expf(m[rh] - mnew);
            float rs = 0.0f;
#pragma unroll
            for (int nt = 0; nt < 8; nt++) {
                sc[nt][i0]     = __expf(sc[nt][i0]     - mnew);
                sc[nt][i0 + 1] = __expf(sc[nt][i0 + 1] - mnew);
                rs += sc[nt][i0] + sc[nt][i0 + 1];
            }
            rs += __shfl_xor_sync(0xffffffffu, rs, 1);
            rs += __shfl_xor_sync(0xffffffffu, rs, 2);
            l[rh] = l[rh] * alpha + rs;
            m[rh] = mnew;
#pragma unroll
            for (int nt = 0; nt < 16; nt++) {
                o[nt][i0]     *= alpha;
                o[nt][i0 + 1] *= alpha;
            }
        }

        // ---- O += P V : P a-fragments directly from registers ----
#pragma unroll
        for (int kk = 0; kk < 4; kk++) {
            uint32_t a[4];
            a[0] = packhf(sc[2 * kk][0],     sc[2 * kk][1]);
            a[1] = packhf(sc[2 * kk][2],     sc[2 * kk][3]);
            a[2] = packhf(sc[2 * kk + 1][0], sc[2 * kk + 1][1]);
            a[3] = packhf(sc[2 * kk + 1][2], sc[2 * kk + 1][3]);
#pragma unroll
            for (int nt = 0; nt < 16; nt++) {
                uint2 b2 = *(const uint2*)&Vf[((kk * 16 + nt) * 32 + lane) * 2];
                uint32_t bb[2] = {b2.x, b2.y};
                mma_fp16(o[nt], a, bb);
            }
        }
    }

    // ---- normalize + write out ----
    float inv0 = 1.0f / l[0];
    float inv1 = 1.0f / l[1];
    size_t row0 = (size_t)(b * S_ + q0 + w * 16 + g);
    size_t row1 = row0 + 8;
#pragma unroll
    for (int nt = 0; nt < 16; nt++) {
        int col = h * HD_ + nt * 8 + 2 * tig;
        *(float2*)&out[row0 * D_ + col] = make_float2(o[nt][0] * inv0, o[nt][1] * inv0);
        *(float2*)&out[row1 * D_ + col] = make_float2(o[nt][2] * inv1, o[nt][3] * inv1);
    }
}

// ---------------------------------------------------------------------------
// Launch
// ---------------------------------------------------------------------------
extern "C" void kernel_launch(void* const* d_in, const int* in_sizes, int n_in,
                              void* d_out, int out_size)
{
    const float* x     = (const float*)d_in[0];
    const float* freqs = (const float*)d_in[1];
    const float* wq    = (const float*)d_in[2];
    const float* wk    = (const float*)d_in[3];
    const float* wv    = (const float*)d_in[4];
    const float* wo    = (const float*)d_in[5];
    const float* nqw   = (const float*)d_in[6];
    const float* nkw   = (const float*)d_in[7];
    float* out = (float*)d_out;

    float *q, *k, *v, *ao;
    cudaGetSymbolAddress((void**)&q,  g_q);
    cudaGetSymbolAddress((void**)&k,  g_k);
    cudaGetSymbolAddress((void**)&v,  g_v);
    cudaGetSymbolAddress((void**)&ao, g_ao);

    dim3 gemm_grid(D_ / 128, MROWS / 128);  // (16, 64)

    int gsm = GEMM_SMEM_WORDS * sizeof(uint32_t);   // 81920 B
    cudaFuncSetAttribute(tbgemm3_nt, cudaFuncAttributeMaxDynamicSharedMemorySize, gsm);

    tbgemm3_nt<<<gemm_grid, 256, gsm>>>(x, wq, q, MROWS, D_, D_);
    tbgemm3_nt<<<gemm_grid, 256, gsm>>>(x, wk, k, MROWS, D_, D_);
    tbgemm3_nt<<<gemm_grid, 256, gsm>>>(x, wv, v, MROWS, D_, D_);

    rmsnorm_rope<<<dim3(MROWS * H_ / 8, 2), 256>>>(q, k, freqs, nqw, nkw);

    cudaFuncSetAttribute(flash_attn_fp16, cudaFuncAttributeMaxDynamicSharedMemorySize,
                         FA_SMEM_BYTES);
    flash_attn_fp16<<<dim3(S_ / 128, H_, B_), 256, FA_SMEM_BYTES>>>(q, k, v, ao);

    tbgemm3_nt<<<gemm_grid, 256, gsm>>>(ao, wo, out, MROWS, D_, D_);
}

// round 12
// speedup vs baseline: 2.2726x; 2.2726x over previous
#include <cuda_runtime.h>
#include <cuda_bf16.h>
#include <cuda_fp16.h>
#include <math.h>
#include <stdint.h>

// Problem constants
#define B_  2
#define S_  4096
#define D_  2048
#define H_  16
#define HD_ 128
#define MROWS (B_ * S_)   // 8192

// Scratch in __device__ globals (allocation-guard-safe)
__device__ float g_q [(size_t)MROWS * D_];
__device__ float g_k [(size_t)MROWS * D_];
__device__ float g_v [(size_t)MROWS * D_];
__device__ float g_ao[(size_t)MROWS * D_];

// ---------------------------------------------------------------------------
// helpers
// ---------------------------------------------------------------------------
__device__ __forceinline__ void mma_bf16(float* c, const uint32_t* a, const uint32_t* b) {
    asm volatile(
        "mma.sync.aligned.m16n8k16.row.col.f32.bf16.bf16.f32 "
        "{%0,%1,%2,%3}, {%4,%5,%6,%7}, {%8,%9}, {%0,%1,%2,%3};\n"
        : "+f"(c[0]), "+f"(c[1]), "+f"(c[2]), "+f"(c[3])
        : "r"(a[0]), "r"(a[1]), "r"(a[2]), "r"(a[3]), "r"(b[0]), "r"(b[1]));
}

__device__ __forceinline__ void mma_fp16(float* c, const uint32_t* a, const uint32_t* b) {
    asm volatile(
        "mma.sync.aligned.m16n8k16.row.col.f32.f16.f16.f32 "
        "{%0,%1,%2,%3}, {%4,%5,%6,%7}, {%8,%9}, {%0,%1,%2,%3};\n"
        : "+f"(c[0]), "+f"(c[1]), "+f"(c[2]), "+f"(c[3])
        : "r"(a[0]), "r"(a[1]), "r"(a[2]), "r"(a[3]), "r"(b[0]), "r"(b[1]));
}

__device__ __forceinline__ uint32_t packbf(float a, float b) {
    __nv_bfloat162 t = __floats2bfloat162_rn(a, b);
    return *(uint32_t*)&t;
}

__device__ __forceinline__ uint32_t packhf(float a, float b) {
    __half2 t = __floats2half2_rn(a, b);
    return *(uint32_t*)&t;
}

__device__ __forceinline__ uint32_t smem_u32(const void* p) {
    uint32_t a;
    asm("{ .reg .u64 t; cvta.to.shared.u64 t, %1; cvt.u32.u64 %0, t; }" : "=r"(a) : "l"(p));
    return a;
}

__device__ __forceinline__ void ldsm_x4(uint32_t* r, uint32_t addr) {
    asm volatile("ldmatrix.sync.aligned.m8n8.x4.shared.b16 {%0,%1,%2,%3}, [%4];"
                 : "=r"(r[0]), "=r"(r[1]), "=r"(r[2]), "=r"(r[3]) : "r"(addr));
}

__device__ __forceinline__ void ldsm_x4_t(uint32_t* r, uint32_t addr) {
    asm volatile("ldmatrix.sync.aligned.m8n8.x4.trans.shared.b16 {%0,%1,%2,%3}, [%4];"
                 : "=r"(r[0]), "=r"(r[1]), "=r"(r[2]), "=r"(r[3]) : "r"(addr));
}

// ---------------------------------------------------------------------------
// 3-pass split-bf16 GEMM (UNCHANGED from R8, validated):
//   C = Ahi*Bhi + Ahi*Blo + Alo*Bhi   (bf16 hi/lo split, fp32 accum)
// 128x128 tile, BK=32, 8 warps (2m x 4n), warp tile 64x32, double-buffered.
// ---------------------------------------------------------------------------
#define LDTW 20
#define GSTAGE (128 * LDTW)
#define GEMM_SMEM_WORDS (8 * GSTAGE)   // 81920 B

__global__ void __launch_bounds__(256, 1) tbgemm3_nt(const float* __restrict__ A,
                                                     const float* __restrict__ Bw,
                                                     float* __restrict__ C,
                                                     int M, int N, int K)
{
    extern __shared__ uint32_t sg[];
    uint32_t* Ah = sg;
    uint32_t* Al = Ah + 2 * GSTAGE;
    uint32_t* Bh = Al + 2 * GSTAGE;
    uint32_t* Bl = Bh + 2 * GSTAGE;

    const int tid    = threadIdx.x;
    const int warp   = tid >> 5;
    const int lane   = tid & 31;
    const int warp_m = warp >> 2;
    const int warp_n = warp & 3;
    const int g      = lane >> 2;
    const int tig    = lane & 3;

    const int bm = blockIdx.y * 128;
    const int bn = blockIdx.x * 128;

    const int lrow = tid >> 3;
    const int lk   = (tid & 7) * 4;
    const int lkw  = (tid & 7) * 2;

    float c[4][4][4];
#pragma unroll
    for (int mi = 0; mi < 4; mi++)
#pragma unroll
        for (int ni = 0; ni < 4; ni++)
#pragma unroll
            for (int j = 0; j < 4; j++) c[mi][ni][j] = 0.0f;

    float4 av[4], bv[4];
#pragma unroll
    for (int r = 0; r < 4; r++) {
        av[r] = *(const float4*)(A  + (size_t)(bm + lrow + 32 * r) * K + lk);
        bv[r] = *(const float4*)(Bw + (size_t)(bn + lrow + 32 * r) * K + lk);
    }

    const int iters = K / 32;
    for (int it = 0; it < iters; it++) {
        const int st = (it & 1) * GSTAGE;

#pragma unroll
        for (int r = 0; r < 4; r++) {
            int base = st + (lrow + 32 * r) * LDTW + lkw;
            {
                float hx = __bfloat162float(__float2bfloat16(av[r].x));
                float hy = __bfloat162float(__float2bfloat16(av[r].y));
                float hz = __bfloat162float(__float2bfloat16(av[r].z));
                float hw = __bfloat162float(__float2bfloat16(av[r].w));
                Ah[base]     = packbf(hx, hy);
                Ah[base + 1] = packbf(hz, hw);
                Al[base]     = packbf(av[r].x - hx, av[r].y - hy);
                Al[base + 1] = packbf(av[r].z - hz, av[r].w - hw);
            }
            {
                float hx = __bfloat162float(__float2bfloat16(bv[r].x));
                float hy = __bfloat162float(__float2bfloat16(bv[r].y));
                float hz = __bfloat162float(__float2bfloat16(bv[r].z));
                float hw = __bfloat162float(__float2bfloat16(bv[r].w));
                Bh[base]     = packbf(hx, hy);
                Bh[base + 1] = packbf(hz, hw);
                Bl[base]     = packbf(bv[r].x - hx, bv[r].y - hy);
                Bl[base + 1] = packbf(bv[r].z - hz, bv[r].w - hw);
            }
        }
        __syncthreads();

        if (it + 1 < iters) {
            const int k0 = (it + 1) * 32;
#pragma unroll
            for (int r = 0; r < 4; r++) {
                av[r] = *(const float4*)(A  + (size_t)(bm + lrow + 32 * r) * K + k0 + lk);
                bv[r] = *(const float4*)(Bw + (size_t)(bn + lrow + 32 * r) * K + k0 + lk);
            }
        }

#pragma unroll
        for (int kk = 0; kk < 2; kk++) {
            uint32_t ahi[4][4], alo[4][4], bhi[4][2], blo[4][2];
#pragma unroll
            for (int mi = 0; mi < 4; mi++) {
                int row = warp_m * 64 + mi * 16;
                int base0 = st + (row + g)     * LDTW + kk * 8 + tig;
                int base1 = st + (row + 8 + g) * LDTW + kk * 8 + tig;
                ahi[mi][0] = Ah[base0];
                ahi[mi][1] = Ah[base1];
                ahi[mi][2] = Ah[base0 + 4];
                ahi[mi][3] = Ah[base1 + 4];
                alo[mi][0] = Al[base0];
                alo[mi][1] = Al[base1];
                alo[mi][2] = Al[base0 + 4];
                alo[mi][3] = Al[base1 + 4];
            }
#pragma unroll
            for (int ni = 0; ni < 4; ni++) {
                int col = warp_n * 32 + ni * 8;
                int base = st + (col + g) * LDTW + kk * 8 + tig;
                bhi[ni][0] = Bh[base];
                bhi[ni][1] = Bh[base + 4];
                blo[ni][0] = Bl[base];
                blo[ni][1] = Bl[base + 4];
            }
#pragma unroll
            for (int mi = 0; mi < 4; mi++)
#pragma unroll
                for (int ni = 0; ni < 4; ni++) {
                    mma_bf16(c[mi][ni], ahi[mi], bhi[ni]);
                    mma_bf16(c[mi][ni], ahi[mi], blo[ni]);
                    mma_bf16(c[mi][ni], alo[mi], bhi[ni]);
                }
        }
        __syncthreads();
    }

#pragma unroll
    for (int mi = 0; mi < 4; mi++) {
#pragma unroll
        for (int ni = 0; ni < 4; ni++) {
            int row0 = bm + warp_m * 64 + mi * 16 + g;
            int col  = bn + warp_n * 32 + ni * 8 + 2 * tig;
            *(float2*)&C[(size_t)row0 * N + col] =
                make_float2(c[mi][ni][0], c[mi][ni][1]);
            *(float2*)&C[(size_t)(row0 + 8) * N + col] =
                make_float2(c[mi][ni][2], c[mi][ni][3]);
        }
    }
}

// ---------------------------------------------------------------------------
// Per-head RMSNorm + RoPE, in place on q and k. (canary: unchanged)
// ---------------------------------------------------------------------------
__global__ void __launch_bounds__(256) rmsnorm_rope(float* __restrict__ qp,
                                                    float* __restrict__ kp,
                                                    const float* __restrict__ freqs,
                                                    const float* __restrict__ wq,
                                                    const float* __restrict__ wk)
{
    float* ptr      = blockIdx.y ? kp : qp;
    const float* w  = blockIdx.y ? wk : wq;

    const int warp = threadIdx.x >> 5;
    const int lane = threadIdx.x & 31;
    const size_t row = (size_t)blockIdx.x * 8 + warp;
    const size_t bs  = row >> 4;

    float4 xv = *(float4*)&ptr[row * HD_ + lane * 4];
    float ss = xv.x * xv.x + xv.y * xv.y + xv.z * xv.z + xv.w * xv.w;
#pragma unroll
    for (int off = 16; off; off >>= 1) ss += __shfl_xor_sync(0xffffffffu, ss, off);
    float r = rsqrtf(ss * (1.0f / 128.0f) + 1e-5f);

    float4 wv = *(const float4*)&w[lane * 4];
    float nr0 = xv.x * r * wv.x;
    float ni0 = xv.y * r * wv.y;
    float nr1 = xv.z * r * wv.z;
    float ni1 = xv.w * r * wv.w;

    const float* f = freqs + bs * HD_;
    float c0 = f[2 * lane],     c1 = f[2 * lane + 1];
    float s0 = f[64 + 2 * lane], s1 = f[64 + 2 * lane + 1];

    float4 o;
    o.x = nr0 * c0 - ni0 * s0;
    o.y = nr0 * s0 + ni0 * c0;
    o.z = nr1 * c1 - ni1 * s1;
    o.w = nr1 * s1 + ni1 * c1;
    *(float4*)&ptr[row * HD_ + lane * 4] = o;
}

// ---------------------------------------------------------------------------
// fp16 flash attention with ldmatrix + natural row-major padded smem.
// Br=128 q rows per CTA, Bc=64 kv per tile, 8 warps x 16 q-rows.
// Smem (half, row stride 136 = 128 + 8 pad -> 272B, conflict-free STS/LDSM):
//   Qs[128][136]  (pre-scaled by 1/sqrt(hd))
//   Ks[64][136], Vs[64][136]  (natural layout; V transposed by ldmatrix.trans)
// Q a-fragments hoisted to registers once (loop-invariant over kv tiles).
// P a-fragments come straight from softmax registers (no smem roundtrip).
// ---------------------------------------------------------------------------
#define QROW 136
#define FA_SMEM_BYTES ((128 + 64 + 64) * QROW * 2)   // 69632 B

__global__ void __launch_bounds__(256, 1) flash_ldsm(const float* __restrict__ q,
                                                     const float* __restrict__ k,
                                                     const float* __restrict__ v,
                                                     float* __restrict__ out)
{
    extern __shared__ __half sh[];
    __half* Qs = sh;                  // [128][QROW]
    __half* Ks = Qs + 128 * QROW;     // [64][QROW]
    __half* Vs = Ks + 64 * QROW;      // [64][QROW]

    const int b    = blockIdx.z;
    const int h    = blockIdx.y;
    const int q0   = blockIdx.x * 128;
    const int tid  = threadIdx.x;
    const int w    = tid >> 5;
    const int lane = tid & 31;
    const int g    = lane >> 2;
    const int tig  = lane & 3;
    const int lt   = lane >> 3;       // ldmatrix tile index 0..3
    const int lr   = lane & 7;        // ldmatrix row within tile

    const uint32_t qb = smem_u32(Qs);
    const uint32_t kb = smem_u32(Ks);
    const uint32_t vb = smem_u32(Vs);

    const float scale = 0.08838834764831845f;  // 1/sqrt(128)

    // ---- Load Q tile -> row-major fp16 smem, pre-scaled (STS.64, no conflicts)
    for (int i = tid; i < 128 * 32; i += 256) {
        int r  = i >> 5;
        int c0 = (i & 31) * 4;
        float4 val = *(const float4*)&q[(size_t)(b * S_ + q0 + r) * D_ + h * HD_ + c0];
        *(uint2*)&Qs[r * QROW + c0] =
            make_uint2(packhf(val.x * scale, val.y * scale),
                       packhf(val.z * scale, val.w * scale));
    }
    __syncthreads();

    // ---- Hoist Q a-fragments (invariant across kv tiles) ----
    uint32_t qa[8][4];
#pragma unroll
    for (int kk = 0; kk < 8; kk++) {
        uint32_t addr = qb + (uint32_t)(((w * 16 + (lt & 1) * 8 + lr) * QROW
                                         + kk * 16 + (lt >> 1) * 8) * 2);
        ldsm_x4(qa[kk], addr);
    }

    float m[2], l[2], o[16][4];
    m[0] = m[1] = -INFINITY;
    l[0] = l[1] = 0.0f;
#pragma unroll
    for (int nt = 0; nt < 16; nt++)
#pragma unroll
        for (int j = 0; j < 4; j++) o[nt][j] = 0.0f;

    for (int kv0 = 0; kv0 < S_; kv0 += 64) {
        __syncthreads();   // Ks/Vs free (prev tile's mma done)

        // ---- Load K,V tiles -> row-major fp16 smem ----
        for (int i = tid; i < 64 * 32; i += 256) {
            int r  = i >> 5;
            int c0 = (i & 31) * 4;
            size_t gbase = (size_t)(b * S_ + kv0 + r) * D_ + h * HD_ + c0;
            float4 kv = *(const float4*)&k[gbase];
            *(uint2*)&Ks[r * QROW + c0] =
                make_uint2(packhf(kv.x, kv.y), packhf(kv.z, kv.w));
            float4 vv = *(const float4*)&v[gbase];
            *(uint2*)&Vs[r * QROW + c0] =
                make_uint2(packhf(vv.x, vv.y), packhf(vv.z, vv.w));
        }
        __syncthreads();

        // ---- S = Q K^T (pre-scaled) ----
        float sc[8][4];
#pragma unroll
        for (int nt = 0; nt < 8; nt++)
#pragma unroll
            for (int j = 0; j < 4; j++) sc[nt][j] = 0.0f;

#pragma unroll
        for (int kk = 0; kk < 8; kk++) {
#pragma unroll
            for (int ntp = 0; ntp < 4; ntp++) {
                uint32_t kbfr[4];
                uint32_t addr = kb + (uint32_t)((((2 * ntp + (lt >> 1)) * 8 + lr) * QROW
                                                 + kk * 16 + (lt & 1) * 8) * 2);
                ldsm_x4(kbfr, addr);
                mma_fp16(sc[2 * ntp],     qa[kk], kbfr);
                mma_fp16(sc[2 * ntp + 1], qa[kk], kbfr + 2);
            }
        }

        // ---- online softmax (rows g and g+8 of this warp's 16-row block) ----
#pragma unroll
        for (int rh = 0; rh < 2; rh++) {
            int i0 = rh * 2;
            float rm = -INFINITY;
#pragma unroll
            for (int nt = 0; nt < 8; nt++)
                rm = fmaxf(rm, fmaxf(sc[nt][i0], sc[nt][i0 + 1]));
            rm = fmaxf(rm, __shfl_xor_sync(0xffffffffu, rm, 1));
            rm = fmaxf(rm, __shfl_xor_sync(0xffffffffu, rm, 2));
            float mnew = fmaxf(m[rh], rm);
            float alpha = __expf(m[rh] - mnew);
            float rs = 0.0f;
#pragma unroll
            for (int nt = 0; nt < 8; nt++) {
                sc[nt][i0]     = __expf(sc[nt][i0]     - mnew);
                sc[nt][i0 + 1] = __expf(sc[nt][i0 + 1] - mnew);
                rs += sc[nt][i0] + sc[nt][i0 + 1];
            }
            rs += __shfl_xor_sync(0xffffffffu, rs, 1);
            rs += __shfl_xor_sync(0xffffffffu, rs, 2);
            l[rh] = l[rh] * alpha + rs;
            m[rh] = mnew;
#pragma unroll
            for (int nt = 0; nt < 16; nt++) {
                o[nt][i0]     *= alpha;
                o[nt][i0 + 1] *= alpha;
            }
        }

        // ---- O += P V : P a-frags from registers, V b-frags via ldmatrix.trans
#pragma unroll
        for (int kk = 0; kk < 4; kk++) {
            uint32_t a[4];
            a[0] = packhf(sc[2 * kk][0],     sc[2 * kk][1]);
            a[1] = packhf(sc[2 * kk][2],     sc[2 * kk][3]);
            a[2] = packhf(sc[2 * kk + 1][0], sc[2 * kk + 1][1]);
            a[3] = packhf(sc[2 * kk + 1][2], sc[2 * kk + 1][3]);
#pragma unroll
            for (int ntp = 0; ntp < 8; ntp++) {
                uint32_t vbfr[4];
                uint32_t addr = vb + (uint32_t)(((kk * 16 + (lt & 1) * 8 + lr) * QROW
                                                 + (2 * ntp + (lt >> 1)) * 8) * 2);
                ldsm_x4_t(vbfr, addr);
                mma_fp16(o[2 * ntp],     a, vbfr);
                mma_fp16(o[2 * ntp + 1], a, vbfr + 2);
            }
        }
    }

    // ---- normalize + write out ----
    float inv0 = 1.0f / l[0];
    float inv1 = 1.0f / l[1];
    size_t row0 = (size_t)(b * S_ + q0 + w * 16 + g);
    size_t row1 = row0 + 8;
#pragma unroll
    for (int nt = 0; nt < 16; nt++) {
        int col = h * HD_ + nt * 8 + 2 * tig;
        *(float2*)&out[row0 * D_ + col] = make_float2(o[nt][0] * inv0, o[nt][1] * inv0);
        *(float2*)&out[row1 * D_ + col] = make_float2(o[nt][2] * inv1, o[nt][3] * inv1);
    }
}

// ---------------------------------------------------------------------------
// Launch
// ---------------------------------------------------------------------------
extern "C" void kernel_launch(void* const* d_in, const int* in_sizes, int n_in,
                              void* d_out, int out_size)
{
    const float* x     = (const float*)d_in[0];
    const float* freqs = (const float*)d_in[1];
    const float* wq    = (const float*)d_in[2];
    const float* wk    = (const float*)d_in[3];
    const float* wv    = (const float*)d_in[4];
    const float* wo    = (const float*)d_in[5];
    const float* nqw   = (const float*)d_in[6];
    const float* nkw   = (const float*)d_in[7];
    float* out = (float*)d_out;

    float *q, *k, *v, *ao;
    cudaGetSymbolAddress((void**)&q,  g_q);
    cudaGetSymbolAddress((void**)&k,  g_k);
    cudaGetSymbolAddress((void**)&v,  g_v);
    cudaGetSymbolAddress((void**)&ao, g_ao);

    dim3 gemm_grid(D_ / 128, MROWS / 128);  // (16, 64)

    int gsm = GEMM_SMEM_WORDS * sizeof(uint32_t);   // 81920 B
    cudaFuncSetAttribute(tbgemm3_nt, cudaFuncAttributeMaxDynamicSharedMemorySize, gsm);

    tbgemm3_nt<<<gemm_grid, 256, gsm>>>(x, wq, q, MROWS, D_, D_);
    tbgemm3_nt<<<gemm_grid, 256, gsm>>>(x, wk, k, MROWS, D_, D_);
    tbgemm3_nt<<<gemm_grid, 256, gsm>>>(x, wv, v, MROWS, D_, D_);

    rmsnorm_rope<<<dim3(MROWS * H_ / 8, 2), 256>>>(q, k, freqs, nqw, nkw);

    cudaFuncSetAttribute(flash_ldsm, cudaFuncAttributeMaxDynamicSharedMemorySize,
                         FA_SMEM_BYTES);
    flash_ldsm<<<dim3(S_ / 128, H_, B_), 256, FA_SMEM_BYTES>>>(q, k, v, ao);

    tbgemm3_nt<<<gemm_grid, 256, gsm>>>(ao, wo, out, MROWS, D_, D_);
}

// round 13
// speedup vs baseline: 2.2742x; 1.0007x over previous
#include <cuda_runtime.h>
#include <cuda_bf16.h>
#include <cuda_fp16.h>
#include <math.h>
#include <stdint.h>

// Problem constants
#define B_  2
#define S_  4096
#define D_  2048
#define H_  16
#define HD_ 128
#define MROWS (B_ * S_)   // 8192

// Scratch in __device__ globals (allocation-guard-safe)
__device__ float g_q [(size_t)MROWS * D_];
__device__ float g_k [(size_t)MROWS * D_];
__device__ float g_v [(size_t)MROWS * D_];
__device__ float g_ao[(size_t)MROWS * D_];

// ---------------------------------------------------------------------------
// helpers
// ---------------------------------------------------------------------------
__device__ __forceinline__ void mma_bf16(float* c, const uint32_t* a, const uint32_t* b) {
    asm volatile(
        "mma.sync.aligned.m16n8k16.row.col.f32.bf16.bf16.f32 "
        "{%0,%1,%2,%3}, {%4,%5,%6,%7}, {%8,%9}, {%0,%1,%2,%3};\n"
        : "+f"(c[0]), "+f"(c[1]), "+f"(c[2]), "+f"(c[3])
        : "r"(a[0]), "r"(a[1]), "r"(a[2]), "r"(a[3]), "r"(b[0]), "r"(b[1]));
}

__device__ __forceinline__ void mma_fp16(float* c, const uint32_t* a, const uint32_t* b) {
    asm volatile(
        "mma.sync.aligned.m16n8k16.row.col.f32.f16.f16.f32 "
        "{%0,%1,%2,%3}, {%4,%5,%6,%7}, {%8,%9}, {%0,%1,%2,%3};\n"
        : "+f"(c[0]), "+f"(c[1]), "+f"(c[2]), "+f"(c[3])
        : "r"(a[0]), "r"(a[1]), "r"(a[2]), "r"(a[3]), "r"(b[0]), "r"(b[1]));
}

__device__ __forceinline__ uint32_t packbf(float a, float b) {
    __nv_bfloat162 t = __floats2bfloat162_rn(a, b);
    return *(uint32_t*)&t;
}

__device__ __forceinline__ uint32_t packhf(float a, float b) {
    __half2 t = __floats2half2_rn(a, b);
    return *(uint32_t*)&t;
}

__device__ __forceinline__ uint32_t smem_u32(const void* p) {
    uint32_t a;
    asm("{ .reg .u64 t; cvta.to.shared.u64 t, %1; cvt.u32.u64 %0, t; }" : "=r"(a) : "l"(p));
    return a;
}

__device__ __forceinline__ void ldsm_x4(uint32_t* r, uint32_t addr) {
    asm volatile("ldmatrix.sync.aligned.m8n8.x4.shared.b16 {%0,%1,%2,%3}, [%4];"
                 : "=r"(r[0]), "=r"(r[1]), "=r"(r[2]), "=r"(r[3]) : "r"(addr));
}

__device__ __forceinline__ void ldsm_x4_t(uint32_t* r, uint32_t addr) {
    asm volatile("ldmatrix.sync.aligned.m8n8.x4.trans.shared.b16 {%0,%1,%2,%3}, [%4];"
                 : "=r"(r[0]), "=r"(r[1]), "=r"(r[2]), "=r"(r[3]) : "r"(addr));
}

// ---------------------------------------------------------------------------
// 3-pass split-bf16 GEMM:  C = Ahi*Bhi + Ahi*Blo + Alo*Bhi  (fp32 accum)
// 128x128 tile, BK=32, 8 warps (2m x 4n), warp tile 64x32, double-buffered.
// R13 change: PASS-MAJOR inner loop — the 3 split passes are hoisted outside
// the (mi,ni) sweep so consecutive mmas hit 16 different accumulators
// (hides HMMA latency instead of serializing 3 same-target mmas).
// ---------------------------------------------------------------------------
#define LDTW 20
#define GSTAGE (128 * LDTW)
#define GEMM_SMEM_WORDS (8 * GSTAGE)   // 81920 B

__global__ void __launch_bounds__(256, 1) tbgemm3_nt(const float* __restrict__ A,
                                                     const float* __restrict__ Bw,
                                                     float* __restrict__ C,
                                                     int M, int N, int K)
{
    extern __shared__ uint32_t sg[];
    uint32_t* Ah = sg;
    uint32_t* Al = Ah + 2 * GSTAGE;
    uint32_t* Bh = Al + 2 * GSTAGE;
    uint32_t* Bl = Bh + 2 * GSTAGE;

    const int tid    = threadIdx.x;
    const int warp   = tid >> 5;
    const int lane   = tid & 31;
    const int warp_m = warp >> 2;
    const int warp_n = warp & 3;
    const int g      = lane >> 2;
    const int tig    = lane & 3;

    const int bm = blockIdx.y * 128;
    const int bn = blockIdx.x * 128;

    const int lrow = tid >> 3;
    const int lk   = (tid & 7) * 4;
    const int lkw  = (tid & 7) * 2;

    float c[4][4][4];
#pragma unroll
    for (int mi = 0; mi < 4; mi++)
#pragma unroll
        for (int ni = 0; ni < 4; ni++)
#pragma unroll
            for (int j = 0; j < 4; j++) c[mi][ni][j] = 0.0f;

    float4 av[4], bv[4];
#pragma unroll
    for (int r = 0; r < 4; r++) {
        av[r] = *(const float4*)(A  + (size_t)(bm + lrow + 32 * r) * K + lk);
        bv[r] = *(const float4*)(Bw + (size_t)(bn + lrow + 32 * r) * K + lk);
    }

    const int iters = K / 32;
    for (int it = 0; it < iters; it++) {
        const int st = (it & 1) * GSTAGE;

#pragma unroll
        for (int r = 0; r < 4; r++) {
            int base = st + (lrow + 32 * r) * LDTW + lkw;
            {
                float hx = __bfloat162float(__float2bfloat16(av[r].x));
                float hy = __bfloat162float(__float2bfloat16(av[r].y));
                float hz = __bfloat162float(__float2bfloat16(av[r].z));
                float hw = __bfloat162float(__float2bfloat16(av[r].w));
                Ah[base]     = packbf(hx, hy);
                Ah[base + 1] = packbf(hz, hw);
                Al[base]     = packbf(av[r].x - hx, av[r].y - hy);
                Al[base + 1] = packbf(av[r].z - hz, av[r].w - hw);
            }
            {
                float hx = __bfloat162float(__float2bfloat16(bv[r].x));
                float hy = __bfloat162float(__float2bfloat16(bv[r].y));
                float hz = __bfloat162float(__float2bfloat16(bv[r].z));
                float hw = __bfloat162float(__float2bfloat16(bv[r].w));
                Bh[base]     = packbf(hx, hy);
                Bh[base + 1] = packbf(hz, hw);
                Bl[base]     = packbf(bv[r].x - hx, bv[r].y - hy);
                Bl[base + 1] = packbf(bv[r].z - hz, bv[r].w - hw);
            }
        }
        __syncthreads();

        if (it + 1 < iters) {
            const int k0 = (it + 1) * 32;
#pragma unroll
            for (int r = 0; r < 4; r++) {
                av[r] = *(const float4*)(A  + (size_t)(bm + lrow + 32 * r) * K + k0 + lk);
                bv[r] = *(const float4*)(Bw + (size_t)(bn + lrow + 32 * r) * K + k0 + lk);
            }
        }

#pragma unroll
        for (int kk = 0; kk < 2; kk++) {
            uint32_t ahi[4][4], alo[4][4], bhi[4][2], blo[4][2];
#pragma unroll
            for (int mi = 0; mi < 4; mi++) {
                int row = warp_m * 64 + mi * 16;
                int base0 = st + (row + g)     * LDTW + kk * 8 + tig;
                int base1 = st + (row + 8 + g) * LDTW + kk * 8 + tig;
                ahi[mi][0] = Ah[base0];
                ahi[mi][1] = Ah[base1];
                ahi[mi][2] = Ah[base0 + 4];
                ahi[mi][3] = Ah[base1 + 4];
                alo[mi][0] = Al[base0];
                alo[mi][1] = Al[base1];
                alo[mi][2] = Al[base0 + 4];
                alo[mi][3] = Al[base1 + 4];
            }
#pragma unroll
            for (int ni = 0; ni < 4; ni++) {
                int col = warp_n * 32 + ni * 8;
                int base = st + (col + g) * LDTW + kk * 8 + tig;
                bhi[ni][0] = Bh[base];
                bhi[ni][1] = Bh[base + 4];
                blo[ni][0] = Bl[base];
                blo[ni][1] = Bl[base + 4];
            }
            // PASS-MAJOR: 16 independent accumulators between same-c reuses
#pragma unroll
            for (int mi = 0; mi < 4; mi++)
#pragma unroll
                for (int ni = 0; ni < 4; ni++)
                    mma_bf16(c[mi][ni], ahi[mi], bhi[ni]);
#pragma unroll
            for (int mi = 0; mi < 4; mi++)
#pragma unroll
                for (int ni = 0; ni < 4; ni++)
                    mma_bf16(c[mi][ni], ahi[mi], blo[ni]);
#pragma unroll
            for (int mi = 0; mi < 4; mi++)
#pragma unroll
                for (int ni = 0; ni < 4; ni++)
                    mma_bf16(c[mi][ni], alo[mi], bhi[ni]);
        }
        __syncthreads();
    }

#pragma unroll
    for (int mi = 0; mi < 4; mi++) {
#pragma unroll
        for (int ni = 0; ni < 4; ni++) {
            int row0 = bm + warp_m * 64 + mi * 16 + g;
            int col  = bn + warp_n * 32 + ni * 8 + 2 * tig;
            *(float2*)&C[(size_t)row0 * N + col] =
                make_float2(c[mi][ni][0], c[mi][ni][1]);
            *(float2*)&C[(size_t)(row0 + 8) * N + col] =
                make_float2(c[mi][ni][2], c[mi][ni][3]);
        }
    }
}

// ---------------------------------------------------------------------------
// Per-head RMSNorm + RoPE, in place on q and k. (canary: unchanged)
// ---------------------------------------------------------------------------
__global__ void __launch_bounds__(256) rmsnorm_rope(float* __restrict__ qp,
                                                    float* __restrict__ kp,
                                                    const float* __restrict__ freqs,
                                                    const float* __restrict__ wq,
                                                    const float* __restrict__ wk)
{
    float* ptr      = blockIdx.y ? kp : qp;
    const float* w  = blockIdx.y ? wk : wq;

    const int warp = threadIdx.x >> 5;
    const int lane = threadIdx.x & 31;
    const size_t row = (size_t)blockIdx.x * 8 + warp;
    const size_t bs  = row >> 4;

    float4 xv = *(float4*)&ptr[row * HD_ + lane * 4];
    float ss = xv.x * xv.x + xv.y * xv.y + xv.z * xv.z + xv.w * xv.w;
#pragma unroll
    for (int off = 16; off; off >>= 1) ss += __shfl_xor_sync(0xffffffffu, ss, off);
    float r = rsqrtf(ss * (1.0f / 128.0f) + 1e-5f);

    float4 wv = *(const float4*)&w[lane * 4];
    float nr0 = xv.x * r * wv.x;
    float ni0 = xv.y * r * wv.y;
    float nr1 = xv.z * r * wv.z;
    float ni1 = xv.w * r * wv.w;

    const float* f = freqs + bs * HD_;
    float c0 = f[2 * lane],     c1 = f[2 * lane + 1];
    float s0 = f[64 + 2 * lane], s1 = f[64 + 2 * lane + 1];

    float4 o;
    o.x = nr0 * c0 - ni0 * s0;
    o.y = nr0 * s0 + ni0 * c0;
    o.z = nr1 * c1 - ni1 * s1;
    o.w = nr1 * s1 + ni1 * c1;
    *(float4*)&ptr[row * HD_ + lane * 4] = o;
}

// ---------------------------------------------------------------------------
// fp16 flash attention with ldmatrix + row-major padded smem (UNCHANGED R12).
// ---------------------------------------------------------------------------
#define QROW 136
#define FA_SMEM_BYTES ((128 + 64 + 64) * QROW * 2)   // 69632 B

__global__ void __launch_bounds__(256, 1) flash_ldsm(const float* __restrict__ q,
                                                     const float* __restrict__ k,
                                                     const float* __restrict__ v,
                                                     float* __restrict__ out)
{
    extern __shared__ __half sh[];
    __half* Qs = sh;                  // [128][QROW]
    __half* Ks = Qs + 128 * QROW;     // [64][QROW]
    __half* Vs = Ks + 64 * QROW;      // [64][QROW]

    const int b    = blockIdx.z;
    const int h    = blockIdx.y;
    const int q0   = blockIdx.x * 128;
    const int tid  = threadIdx.x;
    const int w    = tid >> 5;
    const int lane = tid & 31;
    const int g    = lane >> 2;
    const int tig  = lane & 3;
    const int lt   = lane >> 3;
    const int lr   = lane & 7;

    const uint32_t qb = smem_u32(Qs);
    const uint32_t kb = smem_u32(Ks);
    const uint32_t vb = smem_u32(Vs);

    const float scale = 0.08838834764831845f;  // 1/sqrt(128)

    for (int i = tid; i < 128 * 32; i += 256) {
        int r  = i >> 5;
        int c0 = (i & 31) * 4;
        float4 val = *(const float4*)&q[(size_t)(b * S_ + q0 + r) * D_ + h * HD_ + c0];
        *(uint2*)&Qs[r * QROW + c0] =
            make_uint2(packhf(val.x * scale, val.y * scale),
                       packhf(val.z * scale, val.w * scale));
    }
    __syncthreads();

    uint32_t qa[8][4];
#pragma unroll
    for (int kk = 0; kk < 8; kk++) {
        uint32_t addr = qb + (uint32_t)(((w * 16 + (lt & 1) * 8 + lr) * QROW
                                         + kk * 16 + (lt >> 1) * 8) * 2);
        ldsm_x4(qa[kk], addr);
    }

    float m[2], l[2], o[16][4];
    m[0] = m[1] = -INFINITY;
    l[0] = l[1] = 0.0f;
#pragma unroll
    for (int nt = 0; nt < 16; nt++)
#pragma unroll
        for (int j = 0; j < 4; j++) o[nt][j] = 0.0f;

    for (int kv0 = 0; kv0 < S_; kv0 += 64) {
        __syncthreads();

        for (int i = tid; i < 64 * 32; i += 256) {
            int r  = i >> 5;
            int c0 = (i & 31) * 4;
            size_t gbase = (size_t)(b * S_ + kv0 + r) * D_ + h * HD_ + c0;
            float4 kv = *(const float4*)&k[gbase];
            *(uint2*)&Ks[r * QROW + c0] =
                make_uint2(packhf(kv.x, kv.y), packhf(kv.z, kv.w));
            float4 vv = *(const float4*)&v[gbase];
            *(uint2*)&Vs[r * QROW + c0] =
                make_uint2(packhf(vv.x, vv.y), packhf(vv.z, vv.w));
        }
        __syncthreads();

        float sc[8][4];
#pragma unroll
        for (int nt = 0; nt < 8; nt++)
#pragma unroll
            for (int j = 0; j < 4; j++) sc[nt][j] = 0.0f;

#pragma unroll
        for (int kk = 0; kk < 8; kk++) {
#pragma unroll
            for (int ntp = 0; ntp < 4; ntp++) {
                uint32_t kbfr[4];
                uint32_t addr = kb + (uint32_t)((((2 * ntp + (lt >> 1)) * 8 + lr) * QROW
                                                 + kk * 16 + (lt & 1) * 8) * 2);
                ldsm_x4(kbfr, addr);
                mma_fp16(sc[2 * ntp],     qa[kk], kbfr);
                mma_fp16(sc[2 * ntp + 1], qa[kk], kbfr + 2);
            }
        }

#pragma unroll
        for (int rh = 0; rh < 2; rh++) {
            int i0 = rh * 2;
            float rm = -INFINITY;
#pragma unroll
            for (int nt = 0; nt < 8; nt++)
                rm = fmaxf(rm, fmaxf(sc[nt][i0], sc[nt][i0 + 1]));
            rm = fmaxf(rm, __shfl_xor_sync(0xffffffffu, rm, 1));
            rm = fmaxf(rm, __shfl_xor_sync(0xffffffffu, rm, 2));
            float mnew = fmaxf(m[rh], rm);
            float alpha = __expf(m[rh] - mnew);
            float rs = 0.0f;
#pragma unroll
            for (int nt = 0; nt < 8; nt++) {
                sc[nt][i0]     = __expf(sc[nt][i0]     - mnew);
                sc[nt][i0 + 1] = __expf(sc[nt][i0 + 1] - mnew);
                rs += sc[nt][i0] + sc[nt][i0 + 1];
            }
            rs += __shfl_xor_sync(0xffffffffu, rs, 1);
            rs += __shfl_xor_sync(0xffffffffu, rs, 2);
            l[rh] = l[rh] * alpha + rs;
            m[rh] = mnew;
#pragma unroll
            for (int nt = 0; nt < 16; nt++) {
                o[nt][i0]     *= alpha;
                o[nt][i0 + 1] *= alpha;
            }
        }

#pragma unroll
        for (int kk = 0; kk < 4; kk++) {
            uint32_t a[4];
            a[0] = packhf(sc[2 * kk][0],     sc[2 * kk][1]);
            a[1] = packhf(sc[2 * kk][2],     sc[2 * kk][3]);
            a[2] = packhf(sc[2 * kk + 1][0], sc[2 * kk + 1][1]);
            a[3] = packhf(sc[2 * kk + 1][2], sc[2 * kk + 1][3]);
#pragma unroll
            for (int ntp = 0; ntp < 8; ntp++) {
                uint32_t vbfr[4];
                uint32_t addr = vb + (uint32_t)(((kk * 16 + (lt & 1) * 8 + lr) * QROW
                                                 + (2 * ntp + (lt >> 1)) * 8) * 2);
                ldsm_x4_t(vbfr, addr);
                mma_fp16(o[2 * ntp],     a, vbfr);
                mma_fp16(o[2 * ntp + 1], a, vbfr + 2);
            }
        }
    }

    float inv0 = 1.0f / l[0];
    float inv1 = 1.0f / l[1];
    size_t row0 = (size_t)(b * S_ + q0 + w * 16 + g);
    size_t row1 = row0 + 8;
#pragma unroll
    for (int nt = 0; nt < 16; nt++) {
        int col = h * HD_ + nt * 8 + 2 * tig;
        *(float2*)&out[row0 * D_ + col] = make_float2(o[nt][0] * inv0, o[nt][1] * inv0);
        *(float2*)&out[row1 * D_ + col] = make_float2(o[nt][2] * inv1, o[nt][3] * inv1);
    }
}

// ---------------------------------------------------------------------------
// Launch
// ---------------------------------------------------------------------------
extern "C" void kernel_launch(void* const* d_in, const int* in_sizes, int n_in,
                              void* d_out, int out_size)
{
    const float* x     = (const float*)d_in[0];
    const float* freqs = (const float*)d_in[1];
    const float* wq    = (const float*)d_in[2];
    const float* wk    = (const float*)d_in[3];
    const float* wv    = (const float*)d_in[4];
    const float* wo    = (const float*)d_in[5];
    const float* nqw   = (const float*)d_in[6];
    const float* nkw   = (const float*)d_in[7];
    float* out = (float*)d_out;

    float *q, *k, *v, *ao;
    cudaGetSymbolAddress((void**)&q,  g_q);
    cudaGetSymbolAddress((void**)&k,  g_k);
    cudaGetSymbolAddress((void**)&v,  g_v);
    cudaGetSymbolAddress((void**)&ao, g_ao);

    dim3 gemm_grid(D_ / 128, MROWS / 128);  // (16, 64)

    int gsm = GEMM_SMEM_WORDS * sizeof(uint32_t);   // 81920 B
    cudaFuncSetAttribute(tbgemm3_nt, cudaFuncAttributeMaxDynamicSharedMemorySize, gsm);

    tbgemm3_nt<<<gemm_grid, 256, gsm>>>(x, wq, q, MROWS, D_, D_);
    tbgemm3_nt<<<gemm_grid, 256, gsm>>>(x, wk, k, MROWS, D_, D_);
    tbgemm3_nt<<<gemm_grid, 256, gsm>>>(x, wv, v, MROWS, D_, D_);

    rmsnorm_rope<<<dim3(MROWS * H_ / 8, 2), 256>>>(q, k, freqs, nqw, nkw);

    cudaFuncSetAttribute(flash_ldsm, cudaFuncAttributeMaxDynamicSharedMemorySize,
                         FA_SMEM_BYTES);
    flash_ldsm<<<dim3(S_ / 128, H_, B_), 256, FA_SMEM_BYTES>>>(q, k, v, ao);

    tbgemm3_nt<<<gemm_grid, 256, gsm>>>(ao, wo, out, MROWS, D_, D_);
}

// round 15
// speedup vs baseline: 2.3177x; 1.0191x over previous
#include <cuda_runtime.h>
#include <cuda_bf16.h>
#include <cuda_fp16.h>
#include <math.h>
#include <stdint.h>

// Problem constants
#define B_  2
#define S_  4096
#define D_  2048
#define H_  16
#define HD_ 128
#define MROWS (B_ * S_)   // 8192

// Scratch in __device__ globals (allocation-guard-safe)
__device__ float g_q [(size_t)MROWS * D_];
__device__ float g_k [(size_t)MROWS * D_];
__device__ float g_v [(size_t)MROWS * D_];
__device__ float g_ao[(size_t)MROWS * D_];
__device__ __half g_qh[(size_t)MROWS * D_];
__device__ __half g_kh[(size_t)MROWS * D_];
__device__ __half g_vh[(size_t)MROWS * D_];
__device__ __nv_bfloat16 g_xh [(size_t)MROWS * D_];
__device__ __nv_bfloat16 g_xl [(size_t)MROWS * D_];
__device__ __nv_bfloat16 g_aoh[(size_t)MROWS * D_];
__device__ __nv_bfloat16 g_aol[(size_t)MROWS * D_];
__device__ __nv_bfloat16 g_wqh[(size_t)D_ * D_];
__device__ __nv_bfloat16 g_wql[(size_t)D_ * D_];
__device__ __nv_bfloat16 g_wkh[(size_t)D_ * D_];
__device__ __nv_bfloat16 g_wkl[(size_t)D_ * D_];
__device__ __nv_bfloat16 g_wvh[(size_t)D_ * D_];
__device__ __nv_bfloat16 g_wvl[(size_t)D_ * D_];
__device__ __nv_bfloat16 g_woh[(size_t)D_ * D_];
__device__ __nv_bfloat16 g_wol[(size_t)D_ * D_];

// ---------------------------------------------------------------------------
// helpers
// ---------------------------------------------------------------------------
__device__ __forceinline__ void mma_bf16(float* c, const uint32_t* a, const uint32_t* b) {
    asm volatile(
        "mma.sync.aligned.m16n8k16.row.col.f32.bf16.bf16.f32 "
        "{%0,%1,%2,%3}, {%4,%5,%6,%7}, {%8,%9}, {%0,%1,%2,%3};\n"
        : "+f"(c[0]), "+f"(c[1]), "+f"(c[2]), "+f"(c[3])
        : "r"(a[0]), "r"(a[1]), "r"(a[2]), "r"(a[3]), "r"(b[0]), "r"(b[1]));
}

__device__ __forceinline__ void mma_fp16(float* c, const uint32_t* a, const uint32_t* b) {
    asm volatile(
        "mma.sync.aligned.m16n8k16.row.col.f32.f16.f16.f32 "
        "{%0,%1,%2,%3}, {%4,%5,%6,%7}, {%8,%9}, {%0,%1,%2,%3};\n"
        : "+f"(c[0]), "+f"(c[1]), "+f"(c[2]), "+f"(c[3])
        : "r"(a[0]), "r"(a[1]), "r"(a[2]), "r"(a[3]), "r"(b[0]), "r"(b[1]));
}

__device__ __forceinline__ uint32_t packbf(float a, float b) {
    __nv_bfloat162 t = __floats2bfloat162_rn(a, b);
    return *(uint32_t*)&t;
}

__device__ __forceinline__ uint32_t packhf(float a, float b) {
    __half2 t = __floats2half2_rn(a, b);
    return *(uint32_t*)&t;
}

__device__ __forceinline__ uint32_t smem_u32(const void* p) {
    uint32_t a;
    asm("{ .reg .u64 t; cvta.to.shared.u64 t, %1; cvt.u32.u64 %0, t; }" : "=r"(a) : "l"(p));
    return a;
}

__device__ __forceinline__ void ldsm_x4(uint32_t* r, uint32_t addr) {
    asm volatile("ldmatrix.sync.aligned.m8n8.x4.shared.b16 {%0,%1,%2,%3}, [%4];"
                 : "=r"(r[0]), "=r"(r[1]), "=r"(r[2]), "=r"(r[3]) : "r"(addr));
}

__device__ __forceinline__ void ldsm_x4_t(uint32_t* r, uint32_t addr) {
    asm volatile("ldmatrix.sync.aligned.m8n8.x4.trans.shared.b16 {%0,%1,%2,%3}, [%4];"
                 : "=r"(r[0]), "=r"(r[1]), "=r"(r[2]), "=r"(r[3]) : "r"(addr));
}

#define CP_ASYNC16(dst, src) \
    asm volatile("cp.async.cg.shared.global [%0], [%1], 16;" \
                 :: "r"((uint32_t)(dst)), "l"(src) : "memory")
#define CP_COMMIT() asm volatile("cp.async.commit_group;" ::: "memory")
#define CP_WAIT(n)  asm volatile("cp.async.wait_group %0;" :: "n"(n) : "memory")

// ---------------------------------------------------------------------------
// Prep: split fp32 array into bf16 hi/lo arrays (memory-bound, ~25us each)
// ---------------------------------------------------------------------------
__global__ void __launch_bounds__(256) split_bf(const float* __restrict__ in,
                                               __nv_bfloat16* __restrict__ hi,
                                               __nv_bfloat16* __restrict__ lo,
                                               int n4)
{
    int i = blockIdx.x * 256 + threadIdx.x;
    if (i >= n4) return;
    float4 v = ((const float4*)in)[i];
    float hx = __bfloat162float(__float2bfloat16(v.x));
    float hy = __bfloat162float(__float2bfloat16(v.y));
    float hz = __bfloat162float(__float2bfloat16(v.z));
    float hw = __bfloat162float(__float2bfloat16(v.w));
    ((uint2*)hi)[i] = make_uint2(packbf(hx, hy), packbf(hz, hw));
    ((uint2*)lo)[i] = make_uint2(packbf(v.x - hx, v.y - hy), packbf(v.z - hz, v.w - hw));
}

// ---------------------------------------------------------------------------
// 3-pass split-bf16 GEMM, operands pre-split in gmem:
//   C = Ahi*Bhi + Ahi*Blo + Alo*Bhi  (fp32 accum)
// 128x128 tile, BK=32, 8 warps (2m x 4n), warp tile 64x32, double-buffered.
// ---------------------------------------------------------------------------
#define LDTW 20
#define GSTAGE (128 * LDTW)
#define GEMM_SMEM_WORDS (8 * GSTAGE)   // 81920 B

__global__ void __launch_bounds__(256, 1) tbgemm3p_nt(const __nv_bfloat16* __restrict__ Ahg,
                                                      const __nv_bfloat16* __restrict__ Alg,
                                                      const __nv_bfloat16* __restrict__ Bhg,
                                                      const __nv_bfloat16* __restrict__ Blg,
                                                      float* __restrict__ C,
                                                      int M, int N, int K)
{
    extern __shared__ uint32_t sg[];
    uint32_t* Ah = sg;
    uint32_t* Al = Ah + 2 * GSTAGE;
    uint32_t* Bh = Al + 2 * GSTAGE;
    uint32_t* Bl = Bh + 2 * GSTAGE;

    const uint32_t* Ahw = (const uint32_t*)Ahg;
    const uint32_t* Alw = (const uint32_t*)Alg;
    const uint32_t* Bhw = (const uint32_t*)Bhg;
    const uint32_t* Blw = (const uint32_t*)Blg;
    const int Kw = K >> 1;

    const int tid    = threadIdx.x;
    const int warp   = tid >> 5;
    const int lane   = tid & 31;
    const int warp_m = warp >> 2;
    const int warp_n = warp & 3;
    const int g      = lane >> 2;
    const int tig    = lane & 3;

    const int bm = blockIdx.y * 128;
    const int bn = blockIdx.x * 128;

    const int lrow = tid >> 3;
    const int lkw  = (tid & 7) * 2;

    float c[4][4][4];
#pragma unroll
    for (int mi = 0; mi < 4; mi++)
#pragma unroll
        for (int ni = 0; ni < 4; ni++)
#pragma unroll
            for (int j = 0; j < 4; j++) c[mi][ni][j] = 0.0f;

    uint2 avh[4], avl[4], bvh[4], bvl[4];
#pragma unroll
    for (int r = 0; r < 4; r++) {
        size_t ra = (size_t)(bm + lrow + 32 * r) * Kw + lkw;
        size_t rb = (size_t)(bn + lrow + 32 * r) * Kw + lkw;
        avh[r] = *(const uint2*)(Ahw + ra);
        avl[r] = *(const uint2*)(Alw + ra);
        bvh[r] = *(const uint2*)(Bhw + rb);
        bvl[r] = *(const uint2*)(Blw + rb);
    }

    const int iters = K / 32;
    for (int it = 0; it < iters; it++) {
        const int st = (it & 1) * GSTAGE;

#pragma unroll
        for (int r = 0; r < 4; r++) {
            int base = st + (lrow + 32 * r) * LDTW + lkw;
            Ah[base] = avh[r].x;  Ah[base + 1] = avh[r].y;
            Al[base] = avl[r].x;  Al[base + 1] = avl[r].y;
            Bh[base] = bvh[r].x;  Bh[base + 1] = bvh[r].y;
            Bl[base] = bvl[r].x;  Bl[base + 1] = bvl[r].y;
        }
        __syncthreads();

        if (it + 1 < iters) {
            const int k16 = (it + 1) * 16;
#pragma unroll
            for (int r = 0; r < 4; r++) {
                size_t ra = (size_t)(bm + lrow + 32 * r) * Kw + k16 + lkw;
                size_t rb = (size_t)(bn + lrow + 32 * r) * Kw + k16 + lkw;
                avh[r] = *(const uint2*)(Ahw + ra);
                avl[r] = *(const uint2*)(Alw + ra);
                bvh[r] = *(const uint2*)(Bhw + rb);
                bvl[r] = *(const uint2*)(Blw + rb);
            }
        }

#pragma unroll
        for (int kk = 0; kk < 2; kk++) {
            uint32_t ahi[4][4], alo[4][4], bhi[4][2], blo[4][2];
#pragma unroll
            for (int mi = 0; mi < 4; mi++) {
                int row = warp_m * 64 + mi * 16;
                int base0 = st + (row + g)     * LDTW + kk * 8 + tig;
                int base1 = st + (row + 8 + g) * LDTW + kk * 8 + tig;
                ahi[mi][0] = Ah[base0];
                ahi[mi][1] = Ah[base1];
                ahi[mi][2] = Ah[base0 + 4];
                ahi[mi][3] = Ah[base1 + 4];
                alo[mi][0] = Al[base0];
                alo[mi][1] = Al[base1];
                alo[mi][2] = Al[base0 + 4];
                alo[mi][3] = Al[base1 + 4];
            }
#pragma unroll
            for (int ni = 0; ni < 4; ni++) {
                int col = warp_n * 32 + ni * 8;
                int base = st + (col + g) * LDTW + kk * 8 + tig;
                bhi[ni][0] = Bh[base];
                bhi[ni][1] = Bh[base + 4];
                blo[ni][0] = Bl[base];
                blo[ni][1] = Bl[base + 4];
            }
#pragma unroll
            for (int mi = 0; mi < 4; mi++)
#pragma unroll
                for (int ni = 0; ni < 4; ni++)
                    mma_bf16(c[mi][ni], ahi[mi], bhi[ni]);
#pragma unroll
            for (int mi = 0; mi < 4; mi++)
#pragma unroll
                for (int ni = 0; ni < 4; ni++)
                    mma_bf16(c[mi][ni], ahi[mi], blo[ni]);
#pragma unroll
            for (int mi = 0; mi < 4; mi++)
#pragma unroll
                for (int ni = 0; ni < 4; ni++)
                    mma_bf16(c[mi][ni], alo[mi], bhi[ni]);
        }
        __syncthreads();
    }

#pragma unroll
    for (int mi = 0; mi < 4; mi++) {
#pragma unroll
        for (int ni = 0; ni < 4; ni++) {
            int row0 = bm + warp_m * 64 + mi * 16 + g;
            int col  = bn + warp_n * 32 + ni * 8 + 2 * tig;
            *(float2*)&C[(size_t)row0 * N + col] =
                make_float2(c[mi][ni][0], c[mi][ni][1]);
            *(float2*)&C[(size_t)(row0 + 8) * N + col] =
                make_float2(c[mi][ni][2], c[mi][ni][3]);
        }
    }
}

// ---------------------------------------------------------------------------
// Per-head RMSNorm + RoPE -> fp16 outputs. y=0: q (pre-scaled by 1/sqrt(hd)),
// y=1: k, y=2: v (convert only).
// ---------------------------------------------------------------------------
__global__ void __launch_bounds__(256) rmsnorm_rope_h(const float* __restrict__ qp,
                                                      const float* __restrict__ kp,
                                                      const float* __restrict__ vp,
                                                      const float* __restrict__ freqs,
                                                      const float* __restrict__ wq,
                                                      const float* __restrict__ wk,
                                                      __half* __restrict__ qo,
                                                      __half* __restrict__ ko,
                                                      __half* __restrict__ vo)
{
    const int y = blockIdx.y;
    const int warp = threadIdx.x >> 5;
    const int lane = threadIdx.x & 31;
    const size_t row = (size_t)blockIdx.x * 8 + warp;   // 0 .. B*S*H-1
    const size_t bs  = row >> 4;

    if (y == 2) {
        float4 xv = *(const float4*)&vp[row * HD_ + lane * 4];
        *(uint2*)&vo[row * HD_ + lane * 4] =
            make_uint2(packhf(xv.x, xv.y), packhf(xv.z, xv.w));
        return;
    }

    const float* ptr = y ? kp : qp;
    const float* w   = y ? wk : wq;

    float4 xv = *(const float4*)&ptr[row * HD_ + lane * 4];
    float ss = xv.x * xv.x + xv.y * xv.y + xv.z * xv.z + xv.w * xv.w;
#pragma unroll
    for (int off = 16; off; off >>= 1) ss += __shfl_xor_sync(0xffffffffu, ss, off);
    float r = rsqrtf(ss * (1.0f / 128.0f) + 1e-5f);

    float4 wv = *(const float4*)&w[lane * 4];
    float nr0 = xv.x * r * wv.x;
    float ni0 = xv.y * r * wv.y;
    float nr1 = xv.z * r * wv.z;
    float ni1 = xv.w * r * wv.w;

    const float* f = freqs + bs * HD_;
    float c0 = f[2 * lane],      c1 = f[2 * lane + 1];
    float s0 = f[64 + 2 * lane], s1 = f[64 + 2 * lane + 1];

    float4 o;
    o.x = nr0 * c0 - ni0 * s0;
    o.y = nr0 * s0 + ni0 * c0;
    o.z = nr1 * c1 - ni1 * s1;
    o.w = nr1 * s1 + ni1 * c1;

    if (y == 0) {
        const float scale = 0.08838834764831845f;  // 1/sqrt(128)
        o.x *= scale; o.y *= scale; o.z *= scale; o.w *= scale;
    }
    __half* dst = y ? ko : qo;
    *(uint2*)&dst[row * HD_ + lane * 4] =
        make_uint2(packhf(o.x, o.y), packhf(o.z, o.w));
}

// ---------------------------------------------------------------------------
// fp16 flash attention: ldmatrix fragments + cp.async 2-stage pipelined K/V.
// Br=128 q rows per CTA, Bc=64 kv per tile, 8 warps x 16 q-rows.
// Smem halfs, row stride 136 (272B = 17*16B, cp.async-16 aligned, conflict-free):
//   Qs[128][136], K stages[2][64][136], V stages[2][64][136]
// ---------------------------------------------------------------------------
#define QROW 136
#define FAQ  (128 * QROW)
#define FAT  (64 * QROW)
#define FA_SMEM_BYTES ((FAQ + 4 * FAT) * 2)   // 104448 B

__global__ void __launch_bounds__(256, 1) flash_pipe(const __half* __restrict__ qh,
                                                     const __half* __restrict__ kh,
                                                     const __half* __restrict__ vh,
                                                     float* __restrict__ out)
{
    extern __shared__ __half sh[];

    const int b    = blockIdx.z;
    const int h    = blockIdx.y;
    const int q0   = blockIdx.x * 128;
    const int tid  = threadIdx.x;
    const int w    = tid >> 5;
    const int lane = tid & 31;
    const int g    = lane >> 2;
    const int tig  = lane & 3;
    const int lt   = lane >> 3;
    const int lr   = lane & 7;

    const uint32_t sb  = smem_u32(sh);
    const uint32_t qb  = sb;
    const uint32_t kb0 = sb + FAQ * 2;
    const uint32_t vb0 = sb + (FAQ + 2 * FAT) * 2;

    // ---- Q tile via cp.async (group 1) ----
    for (int i = tid; i < 128 * 16; i += 256) {
        int r = i >> 4;
        int c = (i & 15) * 8;
        CP_ASYNC16(qb + (uint32_t)(r * QROW + c) * 2,
                   qh + (size_t)(b * S_ + q0 + r) * D_ + h * HD_ + c);
    }
    CP_COMMIT();
    // ---- K/V stage 0 (group 2) ----
    for (int i = tid; i < 64 * 16; i += 256) {
        int r = i >> 4;
        int c = (i & 15) * 8;
        size_t go = (size_t)(b * S_ + r) * D_ + h * HD_ + c;
        uint32_t soff = (uint32_t)(r * QROW + c) * 2;
        CP_ASYNC16(kb0 + soff, kh + go);
        CP_ASYNC16(vb0 + soff, vh + go);
    }
    CP_COMMIT();
    CP_WAIT(1);           // Q done (stage0 may still be in flight)
    __syncthreads();

    // ---- Hoist Q a-fragments (invariant across kv tiles) ----
    uint32_t qa[8][4];
#pragma unroll
    for (int kk = 0; kk < 8; kk++) {
        uint32_t addr = qb + (uint32_t)(((w * 16 + (lt & 1) * 8 + lr) * QROW
                                         + kk * 16 + (lt >> 1) * 8) * 2);
        ldsm_x4(qa[kk], addr);
    }

    float m[2], l[2], o[16][4];
    m[0] = m[1] = -INFINITY;
    l[0] = l[1] = 0.0f;
#pragma unroll
    for (int nt = 0; nt < 16; nt++)
#pragma unroll
        for (int j = 0; j < 4; j++) o[nt][j] = 0.0f;

    const int NT = S_ / 64;
    for (int t = 0; t < NT; t++) {
        const int stage = t & 1;

        if (t + 1 < NT) {
            const int nst = (t + 1) & 1;
            const int kv1 = (t + 1) * 64;
            for (int i = tid; i < 64 * 16; i += 256) {
                int r = i >> 4;
                int c = (i & 15) * 8;
                size_t go = (size_t)(b * S_ + kv1 + r) * D_ + h * HD_ + c;
                uint32_t soff = (uint32_t)(nst * FAT + r * QROW + c) * 2;
                CP_ASYNC16(kb0 + soff, kh + go);
                CP_ASYNC16(vb0 + soff, vh + go);
            }
            CP_COMMIT();
            CP_WAIT(1);   // stage t complete, stage t+1 in flight
        } else {
            CP_WAIT(0);   // last tile: drain everything
        }
        __syncthreads();

        const uint32_t kb = kb0 + (uint32_t)(stage * FAT) * 2;
        const uint32_t vb = vb0 + (uint32_t)(stage * FAT) * 2;

        // ---- S = Q K^T (Q pre-scaled) ----
        float sc[8][4];
#pragma unroll
        for (int nt = 0; nt < 8; nt++)
#pragma unroll
            for (int j = 0; j < 4; j++) sc[nt][j] = 0.0f;

#pragma unroll
        for (int kk = 0; kk < 8; kk++) {
#pragma unroll
            for (int ntp = 0; ntp < 4; ntp++) {
                uint32_t kbfr[4];
                uint32_t addr = kb + (uint32_t)((((2 * ntp + (lt >> 1)) * 8 + lr) * QROW
                                                 + kk * 16 + (lt & 1) * 8) * 2);
                ldsm_x4(kbfr, addr);
                mma_fp16(sc[2 * ntp],     qa[kk], kbfr);
                mma_fp16(sc[2 * ntp + 1], qa[kk], kbfr + 2);
            }
        }

        // ---- online softmax ----
#pragma unroll
        for (int rh = 0; rh < 2; rh++) {
            int i0 = rh * 2;
            float rm = -INFINITY;
#pragma unroll
            for (int nt = 0; nt < 8; nt++)
                rm = fmaxf(rm, fmaxf(sc[nt][i0], sc[nt][i0 + 1]));
            rm = fmaxf(rm, __shfl_xor_sync(0xffffffffu, rm, 1));
            rm = fmaxf(rm, __shfl_xor_sync(0xffffffffu, rm, 2));
            float mnew = fmaxf(m[rh], rm);
            float alpha = __expf(m[rh] - mnew);
            float rs = 0.0f;
#pragma unroll
            for (int nt = 0; nt < 8; nt++) {
                sc[nt][i0]     = __expf(sc[nt][i0]     - mnew);
                sc[nt][i0 + 1] = __expf(sc[nt][i0 + 1] - mnew);
                rs += sc[nt][i0] + sc[nt][i0 + 1];
            }
            rs += __shfl_xor_sync(0xffffffffu, rs, 1);
            rs += __shfl_xor_sync(0xffffffffu, rs, 2);
            l[rh] = l[rh] * alpha + rs;
            m[rh] = mnew;
#pragma unroll
            for (int nt = 0; nt < 16; nt++) {
                o[nt][i0]     *= alpha;
                o[nt][i0 + 1] *= alpha;
            }
        }

        // ---- O += P V : P a-frags from registers, V b-frags via ldmatrix.trans
#pragma unroll
        for (int kk = 0; kk < 4; kk++) {
            uint32_t a[4];
            a[0] = packhf(sc[2 * kk][0],     sc[2 * kk][1]);
            a[1] = packhf(sc[2 * kk][2],     sc[2 * kk][3]);
            a[2] = packhf(sc[2 * kk + 1][0], sc[2 * kk + 1][1]);
            a[3] = packhf(sc[2 * kk + 1][2], sc[2 * kk + 1][3]);
#pragma unroll
            for (int ntp = 0; ntp < 8; ntp++) {
                uint32_t vbfr[4];
                uint32_t addr = vb + (uint32_t)(((kk * 16 + (lt & 1) * 8 + lr) * QROW
                                                 + (2 * ntp + (lt >> 1)) * 8) * 2);
                ldsm_x4_t(vbfr, addr);
                mma_fp16(o[2 * ntp],     a, vbfr);
                mma_fp16(o[2 * ntp + 1], a, vbfr + 2);
            }
        }
        __syncthreads();
    }

    float inv0 = 1.0f / l[0];
    float inv1 = 1.0f / l[1];
    size_t row0 = (size_t)(b * S_ + q0 + w * 16 + g);
    size_t row1 = row0 + 8;
#pragma unroll
    for (int nt = 0; nt < 16; nt++) {
        int col = h * HD_ + nt * 8 + 2 * tig;
        *(float2*)&out[row0 * D_ + col] = make_float2(o[nt][0] * inv0, o[nt][1] * inv0);
        *(float2*)&out[row1 * D_ + col] = make_float2(o[nt][2] * inv1, o[nt][3] * inv1);
    }
}

// ---------------------------------------------------------------------------
// Launch
// ---------------------------------------------------------------------------
extern "C" void kernel_launch(void* const* d_in, const int* in_sizes, int n_in,
                              void* d_out, int out_size)
{
    const float* x     = (const float*)d_in[0];
    const float* freqs = (const float*)d_in[1];
    const float* wq    = (const float*)d_in[2];
    const float* wk    = (const float*)d_in[3];
    const float* wv    = (const float*)d_in[4];
    const float* wo    = (const float*)d_in[5];
    float* out = (float*)d_out;

    float *q, *k, *v, *ao;
    __half *qh, *kh, *vh;
    __nv_bfloat16 *xh, *xl, *aoh, *aol;
    __nv_bfloat16 *wqh, *wql, *wkh, *wkl, *wvh, *wvl, *woh, *wol;
    cudaGetSymbolAddress((void**)&q,   g_q);
    cudaGetSymbolAddress((void**)&k,   g_k);
    cudaGetSymbolAddress((void**)&v,   g_v);
    cudaGetSymbolAddress((void**)&ao,  g_ao);
    cudaGetSymbolAddress((void**)&qh,  g_qh);
    cudaGetSymbolAddress((void**)&kh,  g_kh);
    cudaGetSymbolAddress((void**)&vh,  g_vh);
    cudaGetSymbolAddress((void**)&xh,  g_xh);
    cudaGetSymbolAddress((void**)&xl,  g_xl);
    cudaGetSymbolAddress((void**)&aoh, g_aoh);
    cudaGetSymbolAddress((void**)&aol, g_aol);
    cudaGetSymbolAddress((void**)&wqh, g_wqh);
    cudaGetSymbolAddress((void**)&wql, g_wql);
    cudaGetSymbolAddress((void**)&wkh, g_wkh);
    cudaGetSymbolAddress((void**)&wkl, g_wkl);
    cudaGetSymbolAddress((void**)&wvh, g_wvh);
    cudaGetSymbolAddress((void**)&wvl, g_wvl);
    cudaGetSymbolAddress((void**)&woh, g_woh);
    cudaGetSymbolAddress((void**)&wol, g_wol);

    const int n4x = MROWS * D_ / 4;   // 4194304
    const int n4w = D_ * D_ / 4;      // 1048576

    split_bf<<<(n4x + 255) / 256, 256>>>(x,  xh,  xl,  n4x);
    split_bf<<<(n4w + 255) / 256, 256>>>(wq, wqh, wql, n4w);
    split_bf<<<(n4w + 255) / 256, 256>>>(wk, wkh, wkl, n4w);
    split_bf<<<(n4w + 255) / 256, 256>>>(wv, wvh, wvl, n4w);
    split_bf<<<(n4w + 255) / 256, 256>>>(wo, woh, wol, n4w);

    dim3 gemm_grid(D_ / 128, MROWS / 128);  // (16, 64)
    int gsm = GEMM_SMEM_WORDS * sizeof(uint32_t);   // 81920 B
    cudaFuncSetAttribute(tbgemm3p_nt, cudaFuncAttributeMaxDynamicSharedMemorySize, gsm);

    tbgemm3p_nt<<<gemm_grid, 256, gsm>>>(xh, xl, wqh, wql, q, MROWS, D_, D_);
    tbgemm3p_nt<<<gemm_grid, 256, gsm>>>(xh, xl, wkh, wkl, k, MROWS, D_, D_);
    tbgemm3p_nt<<<gemm_grid, 256, gsm>>>(xh, xl, wvh, wvl, v, MROWS, D_, D_);

    rmsnorm_rope_h<<<dim3(MROWS * H_ / 8, 3), 256>>>(
        q, k, v, freqs, (const float*)d_in[6], (const float*)d_in[7], qh, kh, vh);

    cudaFuncSetAttribute(flash_pipe, cudaFuncAttributeMaxDynamicSharedMemorySize,
                         FA_SMEM_BYTES);
    flash_pipe<<<dim3(S_ / 128, H_, B_), 256, FA_SMEM_BYTES>>>(qh, kh, vh, ao);

    split_bf<<<(n4x + 255) / 256, 256>>>(ao, aoh, aol, n4x);
    tbgemm3p_nt<<<gemm_grid, 256, gsm>>>(aoh, aol, woh, wol, out, MROWS, D_, D_);
}